// round 14
// baseline (speedup 1.0000x reference)
#include <cuda_runtime.h>
#include <cstdint>

#define NB    64
#define NC    256
#define NP    4096        // H*W
#define NE    4
#define NO    65          // OUT = CELL*CELL+1
#define NOP   72          // padded OUT
#define NTILE 16          // 256-pixel tiles per batch
#define QB    16          // batches per quarter

// k3 dynamic smem layout (bytes) — R9 proven config
#define XS_STR   264                          // floats per x row
#define WS_STR   76                           // uint2 per w row
#define XS_BYTES (32 * XS_STR * 4)            // 33792
#define WS_BYTES (16 * WS_STR * 8)            // 9728
#define OFF_XS0  0
#define OFF_XS1  XS_BYTES
#define OFF_WS0  (2 * XS_BYTES)               // 67584
#define OFF_WS1  (2 * XS_BYTES + WS_BYTES)    // 77312
#define OFF_BIAS (2 * XS_BYTES + 2 * WS_BYTES)// 87040
#define OFF_SRED (OFF_BIAS + 512)             // 87552
#define SMEM_K3  (OFF_SRED + 8 * 72 * 8)      // 92160

// ---------------- device scratch ----------------
__device__ float  g_pooled[NB * NC];
__device__ int    g_idx[NB];
__device__ float2 g_part2[NO * NB * NTILE];
__device__ float  g_scale[NO];
__device__ float  g_shift[NO];
__device__ __align__(16) uint2 g_Wp[NE * 128 * NOP];   // [e][pair-row][n]

// ---------------- helpers ----------------
__device__ __forceinline__ uint32_t f2tf32(float f) {
    uint32_t r;
    asm("cvt.rna.tf32.f32 %0, %1;" : "=r"(r) : "f"(f));
    return r;
}
__device__ __forceinline__ uint32_t smem_u32(const void* p) {
    uint32_t a;
    asm("{ .reg .u64 t; cvta.to.shared.u64 t, %1; cvt.u32.u64 %0, t; }" : "=r"(a) : "l"(p));
    return a;
}
__device__ __forceinline__ void mma8(float* d, uint2 a02, uint2 a13, uint2 b) {
    asm("mma.sync.aligned.m16n8k8.row.col.f32.tf32.tf32.f32 "
        "{%0,%1,%2,%3}, {%4,%5,%6,%7}, {%8,%9}, {%0,%1,%2,%3};"
        : "+f"(d[0]), "+f"(d[1]), "+f"(d[2]), "+f"(d[3])
        : "r"(a02.x), "r"(a13.x), "r"(a02.y), "r"(a13.y), "r"(b.x), "r"(b.y));
}
#define CP16(dst_u32, src_ptr) \
    asm volatile("cp.async.cg.shared.global [%0], [%1], 16;" :: "r"(dst_u32), "l"(src_ptr) : "memory")
#define CP_COMMIT() asm volatile("cp.async.commit_group;" ::: "memory")
#define CP_WAIT(N)  asm volatile("cp.async.wait_group %0;" :: "n"(N) : "memory")

// ---------------- K0: pack W[e] into tf32 (k,k+4)-pair rows ----------------
__global__ void k0_wprep(const float* __restrict__ w) {
    int idx = blockIdx.x * 256 + threadIdx.x;       // NE*128*72 = 36864
    int e = idx / (128 * NOP);
    int rem = idx - e * (128 * NOP);
    int r = rem / NOP;
    int n = rem - r * NOP;
    int c = r >> 4, rr = r & 15;
    int k = c * 32 + (rr >> 2) * 8 + (rr & 3);
    float lo = (n < NO) ? w[(e * NC + k) * NO + n] : 0.f;
    float hi = (n < NO) ? w[(e * NC + k + 4) * NO + n] : 0.f;
    g_Wp[idx] = make_uint2(f2tf32(lo), f2tf32(hi));
}

// ---------------- K1: pooled mean of relu(x), one quarter of planes ----------------
__global__ void k1_pool(const float* __restrict__ x, int plane0) {
    int plane = plane0 + blockIdx.x;
    const float4* base = (const float4*)(x + (long)plane * NP);
    float s = 0.f;
    #pragma unroll
    for (int i = 0; i < 8; i++) {
        float4 v = base[threadIdx.x + 128 * i];
        s += fmaxf(v.x, 0.f) + fmaxf(v.y, 0.f) + fmaxf(v.z, 0.f) + fmaxf(v.w, 0.f);
    }
    #pragma unroll
    for (int o = 16; o; o >>= 1) s += __shfl_xor_sync(0xffffffffu, s, o);
    __shared__ float red[4];
    if ((threadIdx.x & 31) == 0) red[threadIdx.x >> 5] = s;
    __syncthreads();
    if (threadIdx.x == 0)
        g_pooled[plane] = (red[0] + red[1] + red[2] + red[3]) * (1.f / NP);
}

// ---------------- K2: gate -> argmax expert for QB batches ----------------
__global__ void k2_gate(const float* __restrict__ w_gate,
                        const float* __restrict__ b_gate, int b0) {
    int t = threadIdx.x;                          // 32 threads, 16 active
    if (t >= QB) return;
    int b = b0 + t;
    float lg[NE];
    #pragma unroll
    for (int e = 0; e < NE; e++) lg[e] = b_gate[e];
    const float* pr = g_pooled + b * NC;
    for (int c = 0; c < NC; c++) {
        float pv = pr[c];
        #pragma unroll
        for (int e = 0; e < NE; e++) lg[e] += pv * w_gate[c * NE + e];
    }
    int best = 0; float bv = lg[0];
    #pragma unroll
    for (int e = 1; e < NE; e++)
        if (lg[e] > bv) { bv = lg[e]; best = e; }
    g_idx[b] = best;
}

// ---------------- K3: R9 double-buffer cp.async tf32 GEMM + fused BN partials ----------------
#define ISSUE(c, XOFF, WOFF) do { \
    const float* _xsrc = xsrc_base + (size_t)(c) * 32 * NP; \
    uint32_t _xdst = sbase + (XOFF) + xrow * (XS_STR * 4) + xcol * 16; \
    _Pragma("unroll") \
    for (int _i = 0; _i < 8; _i++) \
        CP16(_xdst + _i * 128, _xsrc + _i * 32); \
    _Pragma("unroll") \
    for (int _it = 0; _it < 3; _it++) { \
        int _ii = tid + _it * 256; \
        if (_ii < 576) { \
            int _r = _ii / 36, _cc = _ii - _r * 36; \
            CP16(sbase + (WOFF) + _r * (WS_STR * 8) + _cc * 16, \
                 (const char*)(wp + ((c) * 16 + _r) * NOP + _cc * 2)); \
        } \
    } \
    CP_COMMIT(); \
} while (0)

#define MMACHUNK(XOFF, WOFF) do { \
    const float* _xsr = (const float*)(sm + (XOFF)); \
    const uint2* _wsp = (const uint2*)(sm + (WOFF)); \
    _Pragma("unroll") \
    for (int _g = 0; _g < 4; _g++) { \
        const float* _xj = _xsr + (_g * 8 + j) * XS_STR + warp_m; \
        uint2 a00, a01, a10, a11; \
        a00.x = f2tf32(fmaxf(_xj[q],      0.f)); a00.y = f2tf32(fmaxf(_xj[4 * XS_STR + q],      0.f)); \
        a01.x = f2tf32(fmaxf(_xj[q + 8],  0.f)); a01.y = f2tf32(fmaxf(_xj[4 * XS_STR + q + 8],  0.f)); \
        a10.x = f2tf32(fmaxf(_xj[q + 16], 0.f)); a10.y = f2tf32(fmaxf(_xj[4 * XS_STR + q + 16], 0.f)); \
        a11.x = f2tf32(fmaxf(_xj[q + 24], 0.f)); a11.y = f2tf32(fmaxf(_xj[4 * XS_STR + q + 24], 0.f)); \
        const uint2* _wrow = _wsp + (_g * 4 + j) * WS_STR + q; \
        _Pragma("unroll") \
        for (int _nt = 0; _nt < 9; _nt++) { \
            uint2 _bb = _wrow[_nt * 8]; \
            mma8(acc[0][_nt], a00, a01, _bb); \
            mma8(acc[1][_nt], a10, a11, _bb); \
        } \
    } \
} while (0)

__global__ __launch_bounds__(256, 2) void k3_mma(const float* __restrict__ x,
                                                 const float* __restrict__ b_experts,
                                                 float* __restrict__ ylog, int b0) {
    extern __shared__ __align__(16) char sm[];
    float*  bias_s = (float*)(sm + OFF_BIAS);
    float2* sred   = (float2*)(sm + OFF_SRED);
    uint32_t sbase = smem_u32(sm);

    int tid = threadIdx.x, lane = tid & 31, wid = tid >> 5;
    int j = lane & 3, q = lane >> 2;
    int b = b0 + blockIdx.y, tile = blockIdx.x;
    int p0 = tile * 256;
    int e = g_idx[b];
    int warp_m = wid * 32;

    const float* xb = x + (size_t)b * NC * NP + p0;
    const uint2* wp = g_Wp + e * (128 * NOP);

    if (tid < NOP) bias_s[tid] = (tid < NO) ? b_experts[e * NO + tid] : 0.f;

    int xrow = tid >> 3;
    int xcol = tid & 7;
    const float* xsrc_base = xb + (size_t)xrow * NP + xcol * 4;

    float acc[2][9][4];
    #pragma unroll
    for (int mt = 0; mt < 2; mt++)
        #pragma unroll
        for (int nt = 0; nt < 9; nt++)
            #pragma unroll
            for (int r = 0; r < 4; r++) acc[mt][nt][r] = 0.f;

    ISSUE(0, OFF_XS0, OFF_WS0);

    for (int cc = 0; cc < 4; cc++) {
        int ce = 2 * cc;
        ISSUE(ce + 1, OFF_XS1, OFF_WS1);
        CP_WAIT(1);
        __syncthreads();
        MMACHUNK(OFF_XS0, OFF_WS0);
        __syncthreads();

        int co = ce + 1;
        if (co < 7) {
            ISSUE(co + 1, OFF_XS0, OFF_WS0);
            CP_WAIT(1);
        } else {
            CP_WAIT(0);
        }
        __syncthreads();
        MMACHUNK(OFF_XS1, OFF_WS1);
        __syncthreads();
    }

    // ---- epilogue: bias, store y, fused per-channel sum/sumsq partials ----
    float sE[9], qE[9], sO[9], qO[9];
    int prow = p0 + warp_m + q;
    #pragma unroll
    for (int nt = 0; nt < 9; nt++) {
        int o0 = nt * 8 + 2 * j;
        float b0f = bias_s[o0], b1f = bias_s[o0 + 1];
        float v00 = acc[0][nt][0] + b0f, v02 = acc[0][nt][2] + b0f;
        float v10 = acc[1][nt][0] + b0f, v12 = acc[1][nt][2] + b0f;
        float v01 = acc[0][nt][1] + b1f, v03 = acc[0][nt][3] + b1f;
        float v11 = acc[1][nt][1] + b1f, v13 = acc[1][nt][3] + b1f;
        if (o0 < NO) {
            float* d = ylog + ((size_t)b * NO + o0) * NP + prow;
            d[0] = v00; d[8] = v02; d[16] = v10; d[24] = v12;
        }
        if (o0 + 1 < NO) {
            float* d = ylog + ((size_t)b * NO + o0 + 1) * NP + prow;
            d[0] = v01; d[8] = v03; d[16] = v11; d[24] = v13;
        }
        sE[nt] = v00 + v02 + v10 + v12;
        qE[nt] = v00 * v00 + v02 * v02 + v10 * v10 + v12 * v12;
        sO[nt] = v01 + v03 + v11 + v13;
        qO[nt] = v01 * v01 + v03 * v03 + v11 * v11 + v13 * v13;
    }
    #pragma unroll
    for (int nt = 0; nt < 9; nt++) {
        #pragma unroll
        for (int off = 4; off < 32; off <<= 1) {
            sE[nt] += __shfl_xor_sync(0xffffffffu, sE[nt], off);
            qE[nt] += __shfl_xor_sync(0xffffffffu, qE[nt], off);
            sO[nt] += __shfl_xor_sync(0xffffffffu, sO[nt], off);
            qO[nt] += __shfl_xor_sync(0xffffffffu, qO[nt], off);
        }
    }
    if (q == 0) {
        #pragma unroll
        for (int nt = 0; nt < 9; nt++) {
            sred[wid * NOP + nt * 8 + 2 * j]     = make_float2(sE[nt], qE[nt]);
            sred[wid * NOP + nt * 8 + 2 * j + 1] = make_float2(sO[nt], qO[nt]);
        }
    }
    __syncthreads();
    if (tid < NO) {
        float ts = 0.f, tq = 0.f;
        #pragma unroll
        for (int w = 0; w < 8; w++) {
            float2 v = sred[w * NOP + tid];
            ts += v.x; tq += v.y;
        }
        g_part2[tid * (NB * NTILE) + b * NTILE + tile] = make_float2(ts, tq);
    }
}

// ---------------- K4b: reduce partials -> BN scale/shift; block NO computes lb_loss ----------------
__global__ void k4b_finalize(const float* __restrict__ gamma,
                             const float* __restrict__ beta,
                             float* __restrict__ loss_out) {
    int o = blockIdx.x;
    int t = threadIdx.x;                 // 256
    if (o == NO) {
        if (t == 0) {
            int cnt[NE] = {0, 0, 0, 0};
            for (int i = 0; i < NB; i++) cnt[g_idx[i]]++;
            float u[NE]; float s = 0.f;
            #pragma unroll
            for (int e = 0; e < NE; e++) { u[e] = (float)cnt[e] / (float)NB + 1e-6f; s += u[e]; }
            float lb = 0.f;
            #pragma unroll
            for (int e = 0; e < NE; e++) {
                float uu = u[e] / s;
                lb += uu * (logf(uu) - logf(0.25f));
            }
            loss_out[0] = lb;
        }
        return;
    }
    const float2* p = g_part2 + o * (NB * NTILE);
    float s = 0.f, qq = 0.f;
    #pragma unroll
    for (int i = 0; i < 4; i++) {
        float2 v = p[t + 256 * i];
        s += v.x; qq += v.y;
    }
    #pragma unroll
    for (int off = 16; off; off >>= 1) {
        s  += __shfl_xor_sync(0xffffffffu, s, off);
        qq += __shfl_xor_sync(0xffffffffu, qq, off);
    }
    __shared__ float2 red[8];
    if ((t & 31) == 0) red[t >> 5] = make_float2(s, qq);
    __syncthreads();
    if (t == 0) {
        float ts = 0.f, tq = 0.f;
        #pragma unroll
        for (int i = 0; i < 8; i++) { ts += red[i].x; tq += red[i].y; }
        const float inv = 1.f / ((float)NB * (float)NP);
        float mean = ts * inv;
        float var = tq * inv - mean * mean;
        float sc = gamma[o] * rsqrtf(var + 1e-5f);
        g_scale[o] = sc;
        g_shift[o] = beta[o] - mean * sc;
    }
}

// ---------------- K5: normalize logits, softmax, pixel-shuffle prob ----------------
__global__ __launch_bounds__(256) void k5_final(float* __restrict__ ylog,
                                                float* __restrict__ prob) {
    int b = blockIdx.y;
    int h = blockIdx.x * 4 + (threadIdx.x >> 6);
    int w = threadIdx.x & 63;
    long base = ((long)b * NO) * NP + h * 64 + w;

    float v[NO];
    float mx = -1e30f;
    #pragma unroll
    for (int o = 0; o < NO; o++) {
        float y = ylog[base + (long)o * NP];
        y = y * g_scale[o] + g_shift[o];
        ylog[base + (long)o * NP] = y;
        v[o] = y;
        mx = fmaxf(mx, y);
    }
    float sum = 0.f;
    #pragma unroll
    for (int o = 0; o < NO; o++) {
        float ev = __expf(v[o] - mx);
        v[o] = ev;
        sum += ev;
    }
    float inv = 1.f / sum;

    float* pb = prob + (long)b * (512 * 512) + (long)(h * 8) * 512 + w * 8;
    #pragma unroll
    for (int r1 = 0; r1 < 8; r1++) {
        float4 a, c;
        a.x = v[r1 * 8 + 0] * inv; a.y = v[r1 * 8 + 1] * inv;
        a.z = v[r1 * 8 + 2] * inv; a.w = v[r1 * 8 + 3] * inv;
        c.x = v[r1 * 8 + 4] * inv; c.y = v[r1 * 8 + 5] * inv;
        c.z = v[r1 * 8 + 6] * inv; c.w = v[r1 * 8 + 7] * inv;
        *(float4*)(pb + (long)r1 * 512)     = a;
        *(float4*)(pb + (long)r1 * 512 + 4) = c;
    }
}

// ---------------- streams/events (created at static init, never during capture) ----------------
struct K3Streams {
    cudaStream_t s2 = nullptr, s3 = nullptr;
    cudaEvent_t evFork = nullptr, evK0 = nullptr, evA = nullptr, evB = nullptr, evC = nullptr;
    K3Streams() {
        cudaStreamCreateWithFlags(&s2, cudaStreamNonBlocking);
        cudaStreamCreateWithFlags(&s3, cudaStreamNonBlocking);
        cudaEventCreateWithFlags(&evFork, cudaEventDisableTiming);
        cudaEventCreateWithFlags(&evK0,   cudaEventDisableTiming);
        cudaEventCreateWithFlags(&evA,    cudaEventDisableTiming);
        cudaEventCreateWithFlags(&evB,    cudaEventDisableTiming);
        cudaEventCreateWithFlags(&evC,    cudaEventDisableTiming);
        cudaFuncSetAttribute(k3_mma, cudaFuncAttributeMaxDynamicSharedMemorySize, SMEM_K3);
    }
};
static K3Streams g_st;

// ---------------- launch ----------------
extern "C" void kernel_launch(void* const* d_in, const int* in_sizes, int n_in,
                              void* d_out, int out_size) {
    const float* x         = (const float*)d_in[0];
    const float* w_experts = (const float*)d_in[1];
    const float* b_experts = (const float*)d_in[2];
    const float* w_gate    = (const float*)d_in[3];
    const float* b_gate    = (const float*)d_in[4];
    const float* gamma     = (const float*)d_in[5];
    const float* beta      = (const float*)d_in[6];

    float* out  = (float*)d_out;
    float* ylog = out;                              // logits: B*NO*NP
    float* prob = out + (long)NB * NO * NP;         // prob:   B*512*512
    float* loss = prob + (long)NB * 512 * 512;      // lb_loss scalar

    cudaStream_t s0 = 0, s2 = g_st.s2, s3 = g_st.s3;

    // fork side streams off the capture-origin stream
    cudaEventRecord(g_st.evFork, s0);
    cudaStreamWaitEvent(s2, g_st.evFork, 0);
    cudaStreamWaitEvent(s3, g_st.evFork, 0);

    // s2: weight prep + quarters 1 and 3
    k0_wprep<<<144, 256, 0, s2>>>(w_experts);
    cudaEventRecord(g_st.evK0, s2);
    k1_pool<<<QB * NC, 128, 0, s2>>>(x, 1 * QB * NC);
    k2_gate<<<1, 32, 0, s2>>>(w_gate, b_gate, 1 * QB);
    cudaEventRecord(g_st.evA, s2);
    k1_pool<<<QB * NC, 128, 0, s2>>>(x, 3 * QB * NC);
    k2_gate<<<1, 32, 0, s2>>>(w_gate, b_gate, 3 * QB);
    cudaEventRecord(g_st.evB, s2);

    // s3: quarter 2
    k1_pool<<<QB * NC, 128, 0, s3>>>(x, 2 * QB * NC);
    k2_gate<<<1, 32, 0, s3>>>(w_gate, b_gate, 2 * QB);
    cudaEventRecord(g_st.evC, s3);

    // s0: quarter 0 pool+gate, then the four k3 quarters as deps arrive
    k1_pool<<<QB * NC, 128, 0, s0>>>(x, 0);
    k2_gate<<<1, 32, 0, s0>>>(w_gate, b_gate, 0);
    cudaStreamWaitEvent(s0, g_st.evK0, 0);
    k3_mma<<<dim3(NTILE, QB), 256, SMEM_K3, s0>>>(x, b_experts, ylog, 0 * QB);
    cudaStreamWaitEvent(s0, g_st.evA, 0);
    k3_mma<<<dim3(NTILE, QB), 256, SMEM_K3, s0>>>(x, b_experts, ylog, 1 * QB);
    cudaStreamWaitEvent(s0, g_st.evC, 0);
    k3_mma<<<dim3(NTILE, QB), 256, SMEM_K3, s0>>>(x, b_experts, ylog, 2 * QB);
    cudaStreamWaitEvent(s0, g_st.evB, 0);
    k3_mma<<<dim3(NTILE, QB), 256, SMEM_K3, s0>>>(x, b_experts, ylog, 3 * QB);

    k4b_finalize<<<NO + 1, 256, 0, s0>>>(gamma, beta, loss);
    k5_final<<<dim3(16, NB), 256, 0, s0>>>(ylog, prob);
}

// round 16
// speedup vs baseline: 1.0402x; 1.0402x over previous
#include <cuda_runtime.h>
#include <cuda_fp16.h>
#include <cstdint>

#define NB    64
#define NC    256
#define NP    4096        // H*W
#define NE    4
#define NO    65          // OUT = CELL*CELL+1
#define NOP   72          // padded OUT
#define NTILE 16          // 256-pixel tiles per batch

// k3 dynamic smem layout (bytes) — R9 proven config
#define XS_STR   264                          // floats per x row
#define WS_STR   76                           // uint2 per w row
#define XS_BYTES (32 * XS_STR * 4)            // 33792
#define WS_BYTES (16 * WS_STR * 8)            // 9728
#define OFF_XS0  0
#define OFF_XS1  XS_BYTES
#define OFF_WS0  (2 * XS_BYTES)               // 67584
#define OFF_WS1  (2 * XS_BYTES + WS_BYTES)    // 77312
#define OFF_BIAS (2 * XS_BYTES + 2 * WS_BYTES)// 87040
#define OFF_SRED (OFF_BIAS + 512)             // 87552
#define SMEM_K3  (OFF_SRED + 8 * 72 * 8)      // 92160

// ---------------- device scratch ----------------
__device__ float  g_pooled[NB * NC];
__device__ int    g_idx[NB];
__device__ float2 g_part2[NO * NB * NTILE];
__device__ float  g_scale[NO];
__device__ float  g_shift[NO];
__device__ __align__(16) uint2 g_Wp[NE * 128 * NOP];   // [e][pair-row][n]
__device__ __half g_yraw[(size_t)NB * NO * NP];        // raw y (pre-BN), fp16

// ---------------- helpers ----------------
__device__ __forceinline__ uint32_t f2tf32(float f) {
    uint32_t r;
    asm("cvt.rna.tf32.f32 %0, %1;" : "=r"(r) : "f"(f));
    return r;
}
__device__ __forceinline__ uint32_t smem_u32(const void* p) {
    uint32_t a;
    asm("{ .reg .u64 t; cvta.to.shared.u64 t, %1; cvt.u32.u64 %0, t; }" : "=r"(a) : "l"(p));
    return a;
}
__device__ __forceinline__ void mma8(float* d, uint2 a02, uint2 a13, uint2 b) {
    asm("mma.sync.aligned.m16n8k8.row.col.f32.tf32.tf32.f32 "
        "{%0,%1,%2,%3}, {%4,%5,%6,%7}, {%8,%9}, {%0,%1,%2,%3};"
        : "+f"(d[0]), "+f"(d[1]), "+f"(d[2]), "+f"(d[3])
        : "r"(a02.x), "r"(a13.x), "r"(a02.y), "r"(a13.y), "r"(b.x), "r"(b.y));
}
#define CP16(dst_u32, src_ptr) \
    asm volatile("cp.async.cg.shared.global [%0], [%1], 16;" :: "r"(dst_u32), "l"(src_ptr) : "memory")
#define CP_COMMIT() asm volatile("cp.async.commit_group;" ::: "memory")
#define CP_WAIT(N)  asm volatile("cp.async.wait_group %0;" :: "n"(N) : "memory")

// ---------------- K0: pack W[e] into tf32 (k,k+4)-pair rows ----------------
__global__ void k0_wprep(const float* __restrict__ w) {
    int idx = blockIdx.x * 256 + threadIdx.x;       // NE*128*72 = 36864
    int e = idx / (128 * NOP);
    int rem = idx - e * (128 * NOP);
    int r = rem / NOP;
    int n = rem - r * NOP;
    int c = r >> 4, rr = r & 15;
    int k = c * 32 + (rr >> 2) * 8 + (rr & 3);
    float lo = (n < NO) ? w[(e * NC + k) * NO + n] : 0.f;
    float hi = (n < NO) ? w[(e * NC + k + 4) * NO + n] : 0.f;
    g_Wp[idx] = make_uint2(f2tf32(lo), f2tf32(hi));
}

// ---------------- K1: pooled[b][c] = mean over pixels of relu(x) ----------------
__global__ void k1_pool(const float* __restrict__ x) {
    int plane = blockIdx.x;
    const float4* base = (const float4*)(x + (long)plane * NP);
    float s = 0.f;
    #pragma unroll
    for (int i = 0; i < 8; i++) {
        float4 v = base[threadIdx.x + 128 * i];
        s += fmaxf(v.x, 0.f) + fmaxf(v.y, 0.f) + fmaxf(v.z, 0.f) + fmaxf(v.w, 0.f);
    }
    #pragma unroll
    for (int o = 16; o; o >>= 1) s += __shfl_xor_sync(0xffffffffu, s, o);
    __shared__ float red[4];
    if ((threadIdx.x & 31) == 0) red[threadIdx.x >> 5] = s;
    __syncthreads();
    if (threadIdx.x == 0)
        g_pooled[plane] = (red[0] + red[1] + red[2] + red[3]) * (1.f / NP);
}

// ---------------- K2: gate -> argmax expert, lb_loss ----------------
__global__ void k2_gate(const float* __restrict__ w_gate,
                        const float* __restrict__ b_gate,
                        float* __restrict__ loss_out) {
    int b = threadIdx.x;                          // 64 threads
    float lg[NE];
    #pragma unroll
    for (int e = 0; e < NE; e++) lg[e] = b_gate[e];
    const float* pr = g_pooled + b * NC;
    for (int c = 0; c < NC; c++) {
        float pv = pr[c];
        #pragma unroll
        for (int e = 0; e < NE; e++) lg[e] += pv * w_gate[c * NE + e];
    }
    int best = 0; float bv = lg[0];
    #pragma unroll
    for (int e = 1; e < NE; e++)
        if (lg[e] > bv) { bv = lg[e]; best = e; }
    g_idx[b] = best;

    __shared__ int sidx[NB];
    sidx[b] = best;
    __syncthreads();
    if (b == 0) {
        int cnt[NE] = {0, 0, 0, 0};
        for (int i = 0; i < NB; i++) cnt[sidx[i]]++;
        float u[NE]; float s = 0.f;
        #pragma unroll
        for (int e = 0; e < NE; e++) { u[e] = (float)cnt[e] / (float)NB + 1e-6f; s += u[e]; }
        float lb = 0.f;
        #pragma unroll
        for (int e = 0; e < NE; e++) {
            float uu = u[e] / s;
            lb += uu * (logf(uu) - logf(0.25f));
        }
        loss_out[0] = lb;
    }
}

// ---------------- K3: R9 double-buffer cp.async tf32 GEMM + fused BN partials ----------------
#define ISSUE(c, XOFF, WOFF) do { \
    const float* _xsrc = xsrc_base + (size_t)(c) * 32 * NP; \
    uint32_t _xdst = sbase + (XOFF) + xrow * (XS_STR * 4) + xcol * 16; \
    _Pragma("unroll") \
    for (int _i = 0; _i < 8; _i++) \
        CP16(_xdst + _i * 128, _xsrc + _i * 32); \
    _Pragma("unroll") \
    for (int _it = 0; _it < 3; _it++) { \
        int _ii = tid + _it * 256; \
        if (_ii < 576) { \
            int _r = _ii / 36, _cc = _ii - _r * 36; \
            CP16(sbase + (WOFF) + _r * (WS_STR * 8) + _cc * 16, \
                 (const char*)(wp + ((c) * 16 + _r) * NOP + _cc * 2)); \
        } \
    } \
    CP_COMMIT(); \
} while (0)

#define MMACHUNK(XOFF, WOFF) do { \
    const float* _xsr = (const float*)(sm + (XOFF)); \
    const uint2* _wsp = (const uint2*)(sm + (WOFF)); \
    _Pragma("unroll") \
    for (int _g = 0; _g < 4; _g++) { \
        const float* _xj = _xsr + (_g * 8 + j) * XS_STR + warp_m; \
        uint2 a00, a01, a10, a11; \
        a00.x = f2tf32(fmaxf(_xj[q],      0.f)); a00.y = f2tf32(fmaxf(_xj[4 * XS_STR + q],      0.f)); \
        a01.x = f2tf32(fmaxf(_xj[q + 8],  0.f)); a01.y = f2tf32(fmaxf(_xj[4 * XS_STR + q + 8],  0.f)); \
        a10.x = f2tf32(fmaxf(_xj[q + 16], 0.f)); a10.y = f2tf32(fmaxf(_xj[4 * XS_STR + q + 16], 0.f)); \
        a11.x = f2tf32(fmaxf(_xj[q + 24], 0.f)); a11.y = f2tf32(fmaxf(_xj[4 * XS_STR + q + 24], 0.f)); \
        const uint2* _wrow = _wsp + (_g * 4 + j) * WS_STR + q; \
        _Pragma("unroll") \
        for (int _nt = 0; _nt < 9; _nt++) { \
            uint2 _bb = _wrow[_nt * 8]; \
            mma8(acc[0][_nt], a00, a01, _bb); \
            mma8(acc[1][_nt], a10, a11, _bb); \
        } \
    } \
} while (0)

__global__ __launch_bounds__(256, 2) void k3_mma(const float* __restrict__ x,
                                                 const float* __restrict__ b_experts) {
    extern __shared__ __align__(16) char sm[];
    float*  bias_s = (float*)(sm + OFF_BIAS);
    float2* sred   = (float2*)(sm + OFF_SRED);
    uint32_t sbase = smem_u32(sm);

    int tid = threadIdx.x, lane = tid & 31, wid = tid >> 5;
    int j = lane & 3, q = lane >> 2;
    int b = blockIdx.y, tile = blockIdx.x;
    int p0 = tile * 256;
    int e = g_idx[b];
    int warp_m = wid * 32;

    const float* xb = x + (size_t)b * NC * NP + p0;
    const uint2* wp = g_Wp + e * (128 * NOP);

    if (tid < NOP) bias_s[tid] = (tid < NO) ? b_experts[e * NO + tid] : 0.f;

    int xrow = tid >> 3;
    int xcol = tid & 7;
    const float* xsrc_base = xb + (size_t)xrow * NP + xcol * 4;

    float acc[2][9][4];
    #pragma unroll
    for (int mt = 0; mt < 2; mt++)
        #pragma unroll
        for (int nt = 0; nt < 9; nt++)
            #pragma unroll
            for (int r = 0; r < 4; r++) acc[mt][nt][r] = 0.f;

    ISSUE(0, OFF_XS0, OFF_WS0);

    for (int cc = 0; cc < 4; cc++) {
        int ce = 2 * cc;
        ISSUE(ce + 1, OFF_XS1, OFF_WS1);
        CP_WAIT(1);
        __syncthreads();
        MMACHUNK(OFF_XS0, OFF_WS0);
        __syncthreads();

        int co = ce + 1;
        if (co < 7) {
            ISSUE(co + 1, OFF_XS0, OFF_WS0);
            CP_WAIT(1);
        } else {
            CP_WAIT(0);
        }
        __syncthreads();
        MMACHUNK(OFF_XS1, OFF_WS1);
        __syncthreads();
    }

    // ---- epilogue: bias, store raw y (fp16), fused per-channel sum/sumsq partials ----
    float sE[9], qE[9], sO[9], qO[9];
    int prow = p0 + warp_m + q;
    #pragma unroll
    for (int nt = 0; nt < 9; nt++) {
        int o0 = nt * 8 + 2 * j;
        float b0f = bias_s[o0], b1f = bias_s[o0 + 1];
        float v00 = acc[0][nt][0] + b0f, v02 = acc[0][nt][2] + b0f;
        float v10 = acc[1][nt][0] + b0f, v12 = acc[1][nt][2] + b0f;
        float v01 = acc[0][nt][1] + b1f, v03 = acc[0][nt][3] + b1f;
        float v11 = acc[1][nt][1] + b1f, v13 = acc[1][nt][3] + b1f;
        if (o0 < NO) {
            __half* d = g_yraw + ((size_t)b * NO + o0) * NP + prow;
            d[0]  = __float2half_rn(v00);
            d[8]  = __float2half_rn(v02);
            d[16] = __float2half_rn(v10);
            d[24] = __float2half_rn(v12);
        }
        if (o0 + 1 < NO) {
            __half* d = g_yraw + ((size_t)b * NO + o0 + 1) * NP + prow;
            d[0]  = __float2half_rn(v01);
            d[8]  = __float2half_rn(v03);
            d[16] = __float2half_rn(v11);
            d[24] = __float2half_rn(v13);
        }
        sE[nt] = v00 + v02 + v10 + v12;
        qE[nt] = v00 * v00 + v02 * v02 + v10 * v10 + v12 * v12;
        sO[nt] = v01 + v03 + v11 + v13;
        qO[nt] = v01 * v01 + v03 * v03 + v11 * v11 + v13 * v13;
    }
    #pragma unroll
    for (int nt = 0; nt < 9; nt++) {
        #pragma unroll
        for (int off = 4; off < 32; off <<= 1) {
            sE[nt] += __shfl_xor_sync(0xffffffffu, sE[nt], off);
            qE[nt] += __shfl_xor_sync(0xffffffffu, qE[nt], off);
            sO[nt] += __shfl_xor_sync(0xffffffffu, sO[nt], off);
            qO[nt] += __shfl_xor_sync(0xffffffffu, qO[nt], off);
        }
    }
    if (q == 0) {
        #pragma unroll
        for (int nt = 0; nt < 9; nt++) {
            sred[wid * NOP + nt * 8 + 2 * j]     = make_float2(sE[nt], qE[nt]);
            sred[wid * NOP + nt * 8 + 2 * j + 1] = make_float2(sO[nt], qO[nt]);
        }
    }
    __syncthreads();
    if (tid < NO) {
        float ts = 0.f, tq = 0.f;
        #pragma unroll
        for (int w = 0; w < 8; w++) {
            float2 v = sred[w * NOP + tid];
            ts += v.x; tq += v.y;
        }
        g_part2[tid * (NB * NTILE) + b * NTILE + tile] = make_float2(ts, tq);
    }
}

// ---------------- K4b: reduce partials, finalize BN scale/shift ----------------
__global__ void k4b_finalize(const float* __restrict__ gamma,
                             const float* __restrict__ beta) {
    int o = blockIdx.x;
    int t = threadIdx.x;                 // 256
    const float2* p = g_part2 + o * (NB * NTILE);
    float s = 0.f, qq = 0.f;
    #pragma unroll
    for (int i = 0; i < 4; i++) {
        float2 v = p[t + 256 * i];
        s += v.x; qq += v.y;
    }
    #pragma unroll
    for (int off = 16; off; off >>= 1) {
        s  += __shfl_xor_sync(0xffffffffu, s, off);
        qq += __shfl_xor_sync(0xffffffffu, qq, off);
    }
    __shared__ float2 red[8];
    if ((t & 31) == 0) red[t >> 5] = make_float2(s, qq);
    __syncthreads();
    if (t == 0) {
        float ts = 0.f, tq = 0.f;
        #pragma unroll
        for (int i = 0; i < 8; i++) { ts += red[i].x; tq += red[i].y; }
        const float inv = 1.f / ((float)NB * (float)NP);
        float mean = ts * inv;
        float var = tq * inv - mean * mean;
        float sc = gamma[o] * rsqrtf(var + 1e-5f);
        g_scale[o] = sc;
        g_shift[o] = beta[o] - mean * sc;
    }
}

// ---------------- K5: read fp16 y, normalize, write logits + softmax pixel-shuffle prob ----------------
__global__ __launch_bounds__(256) void k5_final(float* __restrict__ ylog,
                                                float* __restrict__ prob) {
    int b = blockIdx.y;
    int h = blockIdx.x * 4 + (threadIdx.x >> 6);
    int w = threadIdx.x & 63;
    long base = ((long)b * NO) * NP + h * 64 + w;

    float v[NO];
    float mx = -1e30f;
    #pragma unroll
    for (int o = 0; o < NO; o++) {
        float y = __half2float(g_yraw[base + (long)o * NP]);
        y = y * g_scale[o] + g_shift[o];
        ylog[base + (long)o * NP] = y;
        v[o] = y;
        mx = fmaxf(mx, y);
    }
    float sum = 0.f;
    #pragma unroll
    for (int o = 0; o < NO; o++) {
        float ev = __expf(v[o] - mx);
        v[o] = ev;
        sum += ev;
    }
    float inv = 1.f / sum;

    float* pb = prob + (long)b * (512 * 512) + (long)(h * 8) * 512 + w * 8;
    #pragma unroll
    for (int r1 = 0; r1 < 8; r1++) {
        float4 a, c;
        a.x = v[r1 * 8 + 0] * inv; a.y = v[r1 * 8 + 1] * inv;
        a.z = v[r1 * 8 + 2] * inv; a.w = v[r1 * 8 + 3] * inv;
        c.x = v[r1 * 8 + 4] * inv; c.y = v[r1 * 8 + 5] * inv;
        c.z = v[r1 * 8 + 6] * inv; c.w = v[r1 * 8 + 7] * inv;
        *(float4*)(pb + (long)r1 * 512)     = a;
        *(float4*)(pb + (long)r1 * 512 + 4) = c;
    }
}

// ---------------- launch ----------------
extern "C" void kernel_launch(void* const* d_in, const int* in_sizes, int n_in,
                              void* d_out, int out_size) {
    const float* x         = (const float*)d_in[0];
    const float* w_experts = (const float*)d_in[1];
    const float* b_experts = (const float*)d_in[2];
    const float* w_gate    = (const float*)d_in[3];
    const float* b_gate    = (const float*)d_in[4];
    const float* gamma     = (const float*)d_in[5];
    const float* beta      = (const float*)d_in[6];

    float* out  = (float*)d_out;
    float* ylog = out;                              // logits: B*NO*NP
    float* prob = out + (long)NB * NO * NP;         // prob:   B*512*512
    float* loss = prob + (long)NB * 512 * 512;      // lb_loss scalar

    cudaFuncSetAttribute(k3_mma, cudaFuncAttributeMaxDynamicSharedMemorySize, SMEM_K3);

    k0_wprep<<<144, 256>>>(w_experts);
    k1_pool<<<NB * NC, 128>>>(x);
    k2_gate<<<1, 64>>>(w_gate, b_gate, loss);
    k3_mma<<<dim3(NTILE, NB), 256, SMEM_K3>>>(x, b_experts);
    k4b_finalize<<<NO, 256>>>(gamma, beta);
    k5_final<<<dim3(16, NB), 256>>>(ylog, prob);
}

// round 17
// speedup vs baseline: 1.1295x; 1.0858x over previous
#include <cuda_runtime.h>
#include <cstdint>

#define NB    64
#define NC    256
#define NP    4096        // H*W
#define NE    4
#define NO    65          // OUT = CELL*CELL+1
#define NOP   72          // padded OUT
#define NTILE 16          // 256-pixel tiles per batch

// k3 dynamic smem layout (bytes) — R9 proven config
#define XS_STR   264                          // floats per x row
#define WS_STR   76                           // uint2 per w row
#define XS_BYTES (32 * XS_STR * 4)            // 33792
#define WS_BYTES (16 * WS_STR * 8)            // 9728
#define OFF_XS0  0
#define OFF_XS1  XS_BYTES
#define OFF_WS0  (2 * XS_BYTES)               // 67584
#define OFF_WS1  (2 * XS_BYTES + WS_BYTES)    // 77312
#define OFF_BIAS (2 * XS_BYTES + 2 * WS_BYTES)// 87040
#define OFF_SRED (OFF_BIAS + 512)             // 87552
#define SMEM_K3  (OFF_SRED + 8 * 72 * 8)      // 92160

// ---------------- device scratch ----------------
__device__ float  g_pooled[NB * NC];
__device__ int    g_idx[NB];
__device__ float2 g_part2[NO * NB * NTILE];
__device__ float  g_scale[NO];
__device__ float  g_shift[NO];
__device__ __align__(16) uint2 g_Wp[NE * 128 * NOP];   // [e][pair-row][n]

// ---------------- helpers ----------------
__device__ __forceinline__ uint32_t f2tf32(float f) {
    uint32_t r;
    asm("cvt.rna.tf32.f32 %0, %1;" : "=r"(r) : "f"(f));
    return r;
}
__device__ __forceinline__ uint32_t smem_u32(const void* p) {
    uint32_t a;
    asm("{ .reg .u64 t; cvta.to.shared.u64 t, %1; cvt.u32.u64 %0, t; }" : "=r"(a) : "l"(p));
    return a;
}
__device__ __forceinline__ uint64_t pol_evict_first() {
    uint64_t p;
    asm("createpolicy.fractional.L2::evict_first.b64 %0, 1.0;" : "=l"(p));
    return p;
}
__device__ __forceinline__ uint64_t pol_evict_last() {
    uint64_t p;
    asm("createpolicy.fractional.L2::evict_last.b64 %0, 1.0;" : "=l"(p));
    return p;
}
__device__ __forceinline__ float4 ldg_v4_hint(const float* a, uint64_t pol) {
    float4 v;
    asm volatile("ld.global.nc.L2::cache_hint.v4.f32 {%0,%1,%2,%3}, [%4], %5;"
        : "=f"(v.x), "=f"(v.y), "=f"(v.z), "=f"(v.w) : "l"(a), "l"(pol));
    return v;
}
__device__ __forceinline__ float ldg_f32_hint(const float* a, uint64_t pol) {
    float v;
    asm volatile("ld.global.nc.L2::cache_hint.f32 %0, [%1], %2;" : "=f"(v) : "l"(a), "l"(pol));
    return v;
}
__device__ __forceinline__ void stg_f32_hint(float* a, float v, uint64_t pol) {
    asm volatile("st.global.L2::cache_hint.f32 [%0], %1, %2;" :: "l"(a), "f"(v), "l"(pol) : "memory");
}
__device__ __forceinline__ void stg_v4_hint(float* a, float4 v, uint64_t pol) {
    asm volatile("st.global.L2::cache_hint.v4.f32 [%0], {%1,%2,%3,%4}, %5;"
        :: "l"(a), "f"(v.x), "f"(v.y), "f"(v.z), "f"(v.w), "l"(pol) : "memory");
}
__device__ __forceinline__ void mma8(float* d, uint2 a02, uint2 a13, uint2 b) {
    asm("mma.sync.aligned.m16n8k8.row.col.f32.tf32.tf32.f32 "
        "{%0,%1,%2,%3}, {%4,%5,%6,%7}, {%8,%9}, {%0,%1,%2,%3};"
        : "+f"(d[0]), "+f"(d[1]), "+f"(d[2]), "+f"(d[3])
        : "r"(a02.x), "r"(a13.x), "r"(a02.y), "r"(a13.y), "r"(b.x), "r"(b.y));
}
#define CP16(dst_u32, src_ptr) \
    asm volatile("cp.async.cg.shared.global [%0], [%1], 16;" :: "r"(dst_u32), "l"(src_ptr) : "memory")
#define CP16_HINT(dst_u32, src_ptr, pol) \
    asm volatile("cp.async.cg.shared.global.L2::cache_hint [%0], [%1], 16, %2;" \
        :: "r"(dst_u32), "l"(src_ptr), "l"(pol) : "memory")
#define CP_COMMIT() asm volatile("cp.async.commit_group;" ::: "memory")
#define CP_WAIT(N)  asm volatile("cp.async.wait_group %0;" :: "n"(N) : "memory")

// ---------------- K0: pack W[e] into tf32 (k,k+4)-pair rows ----------------
__global__ void k0_wprep(const float* __restrict__ w) {
    int idx = blockIdx.x * 256 + threadIdx.x;       // NE*128*72 = 36864
    int e = idx / (128 * NOP);
    int rem = idx - e * (128 * NOP);
    int r = rem / NOP;
    int n = rem - r * NOP;
    int c = r >> 4, rr = r & 15;
    int k = c * 32 + (rr >> 2) * 8 + (rr & 3);
    float lo = (n < NO) ? w[(e * NC + k) * NO + n] : 0.f;
    float hi = (n < NO) ? w[(e * NC + k + 4) * NO + n] : 0.f;
    g_Wp[idx] = make_uint2(f2tf32(lo), f2tf32(hi));
}

// ---------------- K1: pooled[b][c] = mean over pixels of relu(x) ----------------
__global__ void k1_pool(const float* __restrict__ x) {
    int plane = blockIdx.x;
    const float* base = x + (long)plane * NP;
    uint64_t pf = pol_evict_first();
    float s = 0.f;
    #pragma unroll
    for (int i = 0; i < 8; i++) {
        float4 v = ldg_v4_hint(base + (threadIdx.x + 128 * i) * 4, pf);
        s += fmaxf(v.x, 0.f) + fmaxf(v.y, 0.f) + fmaxf(v.z, 0.f) + fmaxf(v.w, 0.f);
    }
    #pragma unroll
    for (int o = 16; o; o >>= 1) s += __shfl_xor_sync(0xffffffffu, s, o);
    __shared__ float red[4];
    if ((threadIdx.x & 31) == 0) red[threadIdx.x >> 5] = s;
    __syncthreads();
    if (threadIdx.x == 0)
        g_pooled[plane] = (red[0] + red[1] + red[2] + red[3]) * (1.f / NP);
}

// ---------------- K2: gate -> argmax expert, lb_loss ----------------
__global__ void k2_gate(const float* __restrict__ w_gate,
                        const float* __restrict__ b_gate,
                        float* __restrict__ loss_out) {
    int b = threadIdx.x;                          // 64 threads
    float lg[NE];
    #pragma unroll
    for (int e = 0; e < NE; e++) lg[e] = b_gate[e];
    const float* pr = g_pooled + b * NC;
    for (int c = 0; c < NC; c++) {
        float pv = pr[c];
        #pragma unroll
        for (int e = 0; e < NE; e++) lg[e] += pv * w_gate[c * NE + e];
    }
    int best = 0; float bv = lg[0];
    #pragma unroll
    for (int e = 1; e < NE; e++)
        if (lg[e] > bv) { bv = lg[e]; best = e; }
    g_idx[b] = best;

    __shared__ int sidx[NB];
    sidx[b] = best;
    __syncthreads();
    if (b == 0) {
        int cnt[NE] = {0, 0, 0, 0};
        for (int i = 0; i < NB; i++) cnt[sidx[i]]++;
        float u[NE]; float s = 0.f;
        #pragma unroll
        for (int e = 0; e < NE; e++) { u[e] = (float)cnt[e] / (float)NB + 1e-6f; s += u[e]; }
        float lb = 0.f;
        #pragma unroll
        for (int e = 0; e < NE; e++) {
            float uu = u[e] / s;
            lb += uu * (logf(uu) - logf(0.25f));
        }
        loss_out[0] = lb;
    }
}

// ---------------- K3: R9 double-buffer cp.async tf32 GEMM + fused BN partials ----------------
// x streamed with L2 evict_first; y written with L2 evict_last (keep resident for k5)
#define ISSUE(c, XOFF, WOFF) do { \
    const float* _xsrc = xsrc_base + (size_t)(c) * 32 * NP; \
    uint32_t _xdst = sbase + (XOFF) + xrow * (XS_STR * 4) + xcol * 16; \
    _Pragma("unroll") \
    for (int _i = 0; _i < 8; _i++) \
        CP16_HINT(_xdst + _i * 128, _xsrc + _i * 32, polF); \
    _Pragma("unroll") \
    for (int _it = 0; _it < 3; _it++) { \
        int _ii = tid + _it * 256; \
        if (_ii < 576) { \
            int _r = _ii / 36, _cc = _ii - _r * 36; \
            CP16(sbase + (WOFF) + _r * (WS_STR * 8) + _cc * 16, \
                 (const char*)(wp + ((c) * 16 + _r) * NOP + _cc * 2)); \
        } \
    } \
    CP_COMMIT(); \
} while (0)

#define MMACHUNK(XOFF, WOFF) do { \
    const float* _xsr = (const float*)(sm + (XOFF)); \
    const uint2* _wsp = (const uint2*)(sm + (WOFF)); \
    _Pragma("unroll") \
    for (int _g = 0; _g < 4; _g++) { \
        const float* _xj = _xsr + (_g * 8 + j) * XS_STR + warp_m; \
        uint2 a00, a01, a10, a11; \
        a00.x = f2tf32(fmaxf(_xj[q],      0.f)); a00.y = f2tf32(fmaxf(_xj[4 * XS_STR + q],      0.f)); \
        a01.x = f2tf32(fmaxf(_xj[q + 8],  0.f)); a01.y = f2tf32(fmaxf(_xj[4 * XS_STR + q + 8],  0.f)); \
        a10.x = f2tf32(fmaxf(_xj[q + 16], 0.f)); a10.y = f2tf32(fmaxf(_xj[4 * XS_STR + q + 16], 0.f)); \
        a11.x = f2tf32(fmaxf(_xj[q + 24], 0.f)); a11.y = f2tf32(fmaxf(_xj[4 * XS_STR + q + 24], 0.f)); \
        const uint2* _wrow = _wsp + (_g * 4 + j) * WS_STR + q; \
        _Pragma("unroll") \
        for (int _nt = 0; _nt < 9; _nt++) { \
            uint2 _bb = _wrow[_nt * 8]; \
            mma8(acc[0][_nt], a00, a01, _bb); \
            mma8(acc[1][_nt], a10, a11, _bb); \
        } \
    } \
} while (0)

__global__ __launch_bounds__(256, 2) void k3_mma(const float* __restrict__ x,
                                                 const float* __restrict__ b_experts,
                                                 float* __restrict__ ylog) {
    extern __shared__ __align__(16) char sm[];
    float*  bias_s = (float*)(sm + OFF_BIAS);
    float2* sred   = (float2*)(sm + OFF_SRED);
    uint32_t sbase = smem_u32(sm);
    uint64_t polF = pol_evict_first();
    uint64_t polL = pol_evict_last();

    int tid = threadIdx.x, lane = tid & 31, wid = tid >> 5;
    int j = lane & 3, q = lane >> 2;
    int b = blockIdx.y, tile = blockIdx.x;
    int p0 = tile * 256;
    int e = g_idx[b];
    int warp_m = wid * 32;

    const float* xb = x + (size_t)b * NC * NP + p0;
    const uint2* wp = g_Wp + e * (128 * NOP);

    if (tid < NOP) bias_s[tid] = (tid < NO) ? b_experts[e * NO + tid] : 0.f;

    int xrow = tid >> 3;
    int xcol = tid & 7;
    const float* xsrc_base = xb + (size_t)xrow * NP + xcol * 4;

    float acc[2][9][4];
    #pragma unroll
    for (int mt = 0; mt < 2; mt++)
        #pragma unroll
        for (int nt = 0; nt < 9; nt++)
            #pragma unroll
            for (int r = 0; r < 4; r++) acc[mt][nt][r] = 0.f;

    ISSUE(0, OFF_XS0, OFF_WS0);

    for (int cc = 0; cc < 4; cc++) {
        int ce = 2 * cc;
        ISSUE(ce + 1, OFF_XS1, OFF_WS1);
        CP_WAIT(1);
        __syncthreads();
        MMACHUNK(OFF_XS0, OFF_WS0);
        __syncthreads();

        int co = ce + 1;
        if (co < 7) {
            ISSUE(co + 1, OFF_XS0, OFF_WS0);
            CP_WAIT(1);
        } else {
            CP_WAIT(0);
        }
        __syncthreads();
        MMACHUNK(OFF_XS1, OFF_WS1);
        __syncthreads();
    }

    // ---- epilogue: bias, store y (L2 evict_last), fused per-channel sum/sumsq partials ----
    float sE[9], qE[9], sO[9], qO[9];
    int prow = p0 + warp_m + q;
    #pragma unroll
    for (int nt = 0; nt < 9; nt++) {
        int o0 = nt * 8 + 2 * j;
        float b0f = bias_s[o0], b1f = bias_s[o0 + 1];
        float v00 = acc[0][nt][0] + b0f, v02 = acc[0][nt][2] + b0f;
        float v10 = acc[1][nt][0] + b0f, v12 = acc[1][nt][2] + b0f;
        float v01 = acc[0][nt][1] + b1f, v03 = acc[0][nt][3] + b1f;
        float v11 = acc[1][nt][1] + b1f, v13 = acc[1][nt][3] + b1f;
        if (o0 < NO) {
            float* d = ylog + ((size_t)b * NO + o0) * NP + prow;
            stg_f32_hint(d,      v00, polL);
            stg_f32_hint(d + 8,  v02, polL);
            stg_f32_hint(d + 16, v10, polL);
            stg_f32_hint(d + 24, v12, polL);
        }
        if (o0 + 1 < NO) {
            float* d = ylog + ((size_t)b * NO + o0 + 1) * NP + prow;
            stg_f32_hint(d,      v01, polL);
            stg_f32_hint(d + 8,  v03, polL);
            stg_f32_hint(d + 16, v11, polL);
            stg_f32_hint(d + 24, v13, polL);
        }
        sE[nt] = v00 + v02 + v10 + v12;
        qE[nt] = v00 * v00 + v02 * v02 + v10 * v10 + v12 * v12;
        sO[nt] = v01 + v03 + v11 + v13;
        qO[nt] = v01 * v01 + v03 * v03 + v11 * v11 + v13 * v13;
    }
    #pragma unroll
    for (int nt = 0; nt < 9; nt++) {
        #pragma unroll
        for (int off = 4; off < 32; off <<= 1) {
            sE[nt] += __shfl_xor_sync(0xffffffffu, sE[nt], off);
            qE[nt] += __shfl_xor_sync(0xffffffffu, qE[nt], off);
            sO[nt] += __shfl_xor_sync(0xffffffffu, sO[nt], off);
            qO[nt] += __shfl_xor_sync(0xffffffffu, qO[nt], off);
        }
    }
    if (q == 0) {
        #pragma unroll
        for (int nt = 0; nt < 9; nt++) {
            sred[wid * NOP + nt * 8 + 2 * j]     = make_float2(sE[nt], qE[nt]);
            sred[wid * NOP + nt * 8 + 2 * j + 1] = make_float2(sO[nt], qO[nt]);
        }
    }
    __syncthreads();
    if (tid < NO) {
        float ts = 0.f, tq = 0.f;
        #pragma unroll
        for (int w = 0; w < 8; w++) {
            float2 v = sred[w * NOP + tid];
            ts += v.x; tq += v.y;
        }
        g_part2[tid * (NB * NTILE) + b * NTILE + tile] = make_float2(ts, tq);
    }
}

// ---------------- K4b: reduce partials, finalize BN scale/shift ----------------
__global__ void k4b_finalize(const float* __restrict__ gamma,
                             const float* __restrict__ beta) {
    int o = blockIdx.x;
    int t = threadIdx.x;                 // 256
    const float2* p = g_part2 + o * (NB * NTILE);
    float s = 0.f, qq = 0.f;
    #pragma unroll
    for (int i = 0; i < 4; i++) {
        float2 v = p[t + 256 * i];
        s += v.x; qq += v.y;
    }
    #pragma unroll
    for (int off = 16; off; off >>= 1) {
        s  += __shfl_xor_sync(0xffffffffu, s, off);
        qq += __shfl_xor_sync(0xffffffffu, qq, off);
    }
    __shared__ float2 red[8];
    if ((t & 31) == 0) red[t >> 5] = make_float2(s, qq);
    __syncthreads();
    if (t == 0) {
        float ts = 0.f, tq = 0.f;
        #pragma unroll
        for (int i = 0; i < 8; i++) { ts += red[i].x; tq += red[i].y; }
        const float inv = 1.f / ((float)NB * (float)NP);
        float mean = ts * inv;
        float var = tq * inv - mean * mean;
        float sc = gamma[o] * rsqrtf(var + 1e-5f);
        g_scale[o] = sc;
        g_shift[o] = beta[o] - mean * sc;
    }
}

// ---------------- K5: normalize logits (y read from L2), softmax, pixel-shuffle prob ----------------
__global__ __launch_bounds__(256) void k5_final(float* __restrict__ ylog,
                                                float* __restrict__ prob) {
    int b = blockIdx.y;
    int h = blockIdx.x * 4 + (threadIdx.x >> 6);
    int w = threadIdx.x & 63;
    long base = ((long)b * NO) * NP + h * 64 + w;
    uint64_t pf = pol_evict_first();

    float v[NO];
    float mx = -1e30f;
    #pragma unroll
    for (int o = 0; o < NO; o++) {
        float y = ldg_f32_hint(ylog + base + (long)o * NP, pf);
        y = y * g_scale[o] + g_shift[o];
        stg_f32_hint(ylog + base + (long)o * NP, y, pf);
        v[o] = y;
        mx = fmaxf(mx, y);
    }
    float sum = 0.f;
    #pragma unroll
    for (int o = 0; o < NO; o++) {
        float ev = __expf(v[o] - mx);
        v[o] = ev;
        sum += ev;
    }
    float inv = 1.f / sum;

    float* pb = prob + (long)b * (512 * 512) + (long)(h * 8) * 512 + w * 8;
    #pragma unroll
    for (int r1 = 0; r1 < 8; r1++) {
        float4 a, c;
        a.x = v[r1 * 8 + 0] * inv; a.y = v[r1 * 8 + 1] * inv;
        a.z = v[r1 * 8 + 2] * inv; a.w = v[r1 * 8 + 3] * inv;
        c.x = v[r1 * 8 + 4] * inv; c.y = v[r1 * 8 + 5] * inv;
        c.z = v[r1 * 8 + 6] * inv; c.w = v[r1 * 8 + 7] * inv;
        stg_v4_hint(pb + (long)r1 * 512,     a, pf);
        stg_v4_hint(pb + (long)r1 * 512 + 4, c, pf);
    }
}

// ---------------- launch ----------------
extern "C" void kernel_launch(void* const* d_in, const int* in_sizes, int n_in,
                              void* d_out, int out_size) {
    const float* x         = (const float*)d_in[0];
    const float* w_experts = (const float*)d_in[1];
    const float* b_experts = (const float*)d_in[2];
    const float* w_gate    = (const float*)d_in[3];
    const float* b_gate    = (const float*)d_in[4];
    const float* gamma     = (const float*)d_in[5];
    const float* beta      = (const float*)d_in[6];

    float* out  = (float*)d_out;
    float* ylog = out;                              // logits: B*NO*NP
    float* prob = out + (long)NB * NO * NP;         // prob:   B*512*512
    float* loss = prob + (long)NB * 512 * 512;      // lb_loss scalar

    cudaFuncSetAttribute(k3_mma, cudaFuncAttributeMaxDynamicSharedMemorySize, SMEM_K3);

    k0_wprep<<<144, 256>>>(w_experts);
    k1_pool<<<NB * NC, 128>>>(x);
    k2_gate<<<1, 64>>>(w_gate, b_gate, loss);
    k3_mma<<<dim3(NTILE, NB), 256, SMEM_K3>>>(x, b_experts, ylog);
    k4b_finalize<<<NO, 256>>>(gamma, beta);
    k5_final<<<dim3(16, NB), 256>>>(ylog, prob);
}